// round 3
// baseline (speedup 1.0000x reference)
#include <cuda_runtime.h>
#include <math.h>
#include <stdint.h>

// ---------------- problem constants ----------------
#define DDIM 512
#define TSTEPS 1024
#define BATCH 8
#define NSLOT 32
#define CPB 16            // CTAs per batch for the scan
#define SLICE 32          // d-slice per CTA (CPB*SLICE == DDIM)
#define MROWS (BATCH*TSTEPS)
#define SCAN_THREADS 512

// ---------------- static device scratch (no allocations allowed) ----------------
__device__ float g_xproj[(size_t)MROWS * DDIM];  // silu(xz[:, :512])
__device__ float g_siluz[(size_t)MROWS * DDIM];  // silu(xz[:, 512:])
__device__ float g_xw   [(size_t)MROWS * DDIM];  // x_proj @ W_x^T
__device__ float g_hs   [(size_t)MROWS * DDIM];  // scan hidden outputs
__device__ float g_ex[BATCH][CPB][96];           // exchange: [0:32] r_part, [32:64] h_new, [64:96] w_part
__device__ int   g_cnt[BATCH];                   // per-batch barrier counters

__device__ __forceinline__ float siluf(float v) { return v / (1.0f + __expf(-v)); }

// ---------------- exact 1.5-entmax over 32 values, one per lane ----------------
__device__ __forceinline__ float entmax15_warp(float z, int lane) {
    const unsigned F = 0xffffffffu;
    float x = 0.5f * z;
    float m = x;
#pragma unroll
    for (int o = 16; o > 0; o >>= 1) m = fmaxf(m, __shfl_xor_sync(F, m, o));
    x -= m;
    // ascending bitonic sort across the warp
    float v = x;
#pragma unroll
    for (int k = 2; k <= 32; k <<= 1) {
#pragma unroll
        for (int j = k >> 1; j > 0; j >>= 1) {
            float o = __shfl_xor_sync(F, v, j);
            bool up = ((lane & k) == 0);
            if (((lane & j) == 0) == up) v = fminf(v, o);
            else                         v = fmaxf(v, o);
        }
    }
    float zs = __shfl_sync(F, v, 31 - lane);   // descending sorted value at this lane
    // inclusive prefix sums of zs and zs^2
    float s = zs, s2 = zs * zs;
#pragma unroll
    for (int d = 1; d < 32; d <<= 1) {
        float t1 = __shfl_up_sync(F, s, d);
        float t2 = __shfl_up_sync(F, s2, d);
        if (lane >= d) { s += t1; s2 += t2; }
    }
    float k1     = (float)(lane + 1);
    float mean   = s / k1;
    float meansq = s2 / k1;
    float ss     = k1 * (meansq - mean * mean);
    float delta  = (1.0f - ss) / k1;
    float tau    = mean - sqrtf(fmaxf(delta, 0.0f));
    unsigned bal = __ballot_sync(F, tau <= zs);
    int support  = __popc(bal) - 1;
    float tau_star = __shfl_sync(F, tau, support);
    float p = fmaxf(x - tau_star, 0.0f);
    return p * p;
}

// ---------------- SGEMM: C[M,N] = A[M,K] @ B[N,K]^T ----------------
// MODE 0: A = x (ext),     epilogue: silu -> g_xproj (n<512) / g_siluz (n>=512)
// MODE 1: A = g_xproj,     epilogue: -> g_xw
// MODE 2: A = g_hs*g_siluz (fused on load), epilogue: -> Cout (d_out)
template <int MODE>
__global__ void __launch_bounds__(256)
sgemm(const float* __restrict__ Aext, const float* __restrict__ Bmat,
      float* __restrict__ Cout, int M, int N, int K)
{
    __shared__ float As[8 * 128];
    __shared__ float Bs[8 * 128];

    const int tid = threadIdx.x;
    const int bm = blockIdx.y * 128;
    const int bn = blockIdx.x * 128;
    const int lrow = tid >> 1;
    const int lk   = (tid & 1) * 4;
    const int tx = tid & 15;
    const int ty = tid >> 4;

    const float* A = (MODE == 0) ? Aext : ((MODE == 1) ? g_xproj : g_hs);

    float acc[8][8];
#pragma unroll
    for (int i = 0; i < 8; i++)
#pragma unroll
        for (int j = 0; j < 8; j++) acc[i][j] = 0.0f;

    for (int kt = 0; kt < K; kt += 8) {
        float4 av = *(const float4*)(A + (size_t)(bm + lrow) * K + kt + lk);
        if (MODE == 2) {
            float4 sv = *(const float4*)(g_siluz + (size_t)(bm + lrow) * K + kt + lk);
            av.x *= sv.x; av.y *= sv.y; av.z *= sv.z; av.w *= sv.w;
        }
        As[(lk + 0) * 128 + lrow] = av.x;
        As[(lk + 1) * 128 + lrow] = av.y;
        As[(lk + 2) * 128 + lrow] = av.z;
        As[(lk + 3) * 128 + lrow] = av.w;
        float4 bv = *(const float4*)(Bmat + (size_t)(bn + lrow) * K + kt + lk);
        Bs[(lk + 0) * 128 + lrow] = bv.x;
        Bs[(lk + 1) * 128 + lrow] = bv.y;
        Bs[(lk + 2) * 128 + lrow] = bv.z;
        Bs[(lk + 3) * 128 + lrow] = bv.w;
        __syncthreads();
#pragma unroll
        for (int kk = 0; kk < 8; kk++) {
            float af[8], bf[8];
            *(float4*)(af + 0) = *(const float4*)(As + kk * 128 + ty * 8 + 0);
            *(float4*)(af + 4) = *(const float4*)(As + kk * 128 + ty * 8 + 4);
            *(float4*)(bf + 0) = *(const float4*)(Bs + kk * 128 + tx * 8 + 0);
            *(float4*)(bf + 4) = *(const float4*)(Bs + kk * 128 + tx * 8 + 4);
#pragma unroll
            for (int i = 0; i < 8; i++)
#pragma unroll
                for (int j = 0; j < 8; j++)
                    acc[i][j] = fmaf(af[i], bf[j], acc[i][j]);
        }
        __syncthreads();
    }

#pragma unroll
    for (int i = 0; i < 8; i++) {
        const size_t m = (size_t)(bm + ty * 8 + i);
#pragma unroll
        for (int j = 0; j < 8; j++) {
            const int gn = bn + tx * 8 + j;
            float v = acc[i][j];
            if (MODE == 0) {
                if (gn < DDIM) g_xproj[m * DDIM + gn] = siluf(v);
                else           g_siluz[m * DDIM + (gn - DDIM)] = siluf(v);
            } else if (MODE == 1) {
                g_xw[m * DDIM + gn] = v;
            } else {
                Cout[m * DDIM + gn] = v;
            }
        }
    }
}

// ---------------- init: reset barrier counters ----------------
__global__ void init_kernel() {
    if (threadIdx.x < BATCH) g_cnt[threadIdx.x] = 0;
}

// ---------------- dual-memory scan ----------------
// grid = BATCH*CPB CTAs, 512 threads each. CTA owns a 32-wide d-slice:
// W_h/W_write row slices cached in SMEM; tape sharded by d; cross-CTA
// reductions via L2-resident exchange + per-batch counter barriers.
__global__ void __launch_bounds__(SCAN_THREADS)
scan_kernel(const float* __restrict__ W_h, const float* __restrict__ W_write,
            const float* __restrict__ b_h, float* __restrict__ dout)
{
    extern __shared__ float sm[];
    float* Wh_s   = sm;                 // 32*512
    float* Ww_s   = Wh_s + SLICE * DDIM; // 32*512
    float* tape_s = Ww_s + SLICE * DDIM; // 32*33 (padded rows)
    float* work_s = tape_s + NSLOT * 33; // 512
    float* hpre_s = work_s + DDIM;       // 32
    float* hnew_s = hpre_s + 32;         // 32
    float* a_s    = hnew_s + 32;         // 32
    float* bv_s   = a_s + 32;            // 32
    float* wval_s = bv_s + 32;           // 32

    const int tid  = threadIdx.x;
    const int wid  = tid >> 5;
    const int lane = tid & 31;
    const int b    = blockIdx.x / CPB;
    const int c    = blockIdx.x % CPB;
    const int dbase = c * SLICE;
    const float scale = 0.044194173824159216f;  // 1/sqrt(512)
    const unsigned F = 0xffffffffu;

    // cache weight slices (rows dbase..dbase+31) in SMEM
    for (int i = tid; i < SLICE * DDIM / 4; i += SCAN_THREADS) {
        ((float4*)Wh_s)[i] = ((const float4*)(W_h     + (size_t)dbase * DDIM))[i];
        ((float4*)Ww_s)[i] = ((const float4*)(W_write + (size_t)dbase * DDIM))[i];
    }
    for (int i = tid; i < NSLOT * 33; i += SCAN_THREADS) tape_s[i] = 0.0f;
    for (int i = tid; i < DDIM; i += SCAN_THREADS) work_s[i] = 0.0f;
    __syncthreads();

    volatile int* cntp = (volatile int*)&g_cnt[b];
    int sync_id = 0;
    const int o0 = 2 * wid, o1 = o0 + 1;

    for (int t = 0; t < TSTEPS; t++) {
        // ---- Phase A: h_pre slice = W_h_slice @ work + xw + b_h ----
        {
            float acc0 = 0.0f, acc1 = 0.0f;
            const float* wr0 = Wh_s + o0 * DDIM;
            const float* wr1 = Wh_s + o1 * DDIM;
#pragma unroll
            for (int kk = 0; kk < 16; kk++) {
                int d = lane + kk * 32;
                float wv = work_s[d];
                acc0 = fmaf(wr0[d], wv, acc0);
                acc1 = fmaf(wr1[d], wv, acc1);
            }
#pragma unroll
            for (int o = 16; o > 0; o >>= 1) {
                acc0 += __shfl_xor_sync(F, acc0, o);
                acc1 += __shfl_xor_sync(F, acc1, o);
            }
            if (lane == 0) {
                size_t xwoff = ((size_t)b * TSTEPS + t) * DDIM + dbase;
                hpre_s[o0] = acc0 + g_xw[xwoff + o0] + b_h[dbase + o0];
                hpre_s[o1] = acc1 + g_xw[xwoff + o1] + b_h[dbase + o1];
            }
        }
        __syncthreads();
        // r partials over local d-slice
        {
            float rp0 = tape_s[o0 * 33 + lane] * hpre_s[lane];
            float rp1 = tape_s[o1 * 33 + lane] * hpre_s[lane];
#pragma unroll
            for (int o = 16; o > 0; o >>= 1) {
                rp0 += __shfl_xor_sync(F, rp0, o);
                rp1 += __shfl_xor_sync(F, rp1, o);
            }
            if (lane == 0) {
                g_ex[b][c][o0] = rp0;
                g_ex[b][c][o1] = rp1;
            }
        }
        __syncthreads();
        sync_id++;
        if (tid == 0) {
            __threadfence();
            atomicAdd(&g_cnt[b], 1);
            while (*cntp < CPB * sync_id) { }
            __threadfence();
        }
        __syncthreads();

        // ---- Phase B: reduce r, entmax, read, h_new, w partials ----
        if (wid == 0) {
            float rs = 0.0f;
#pragma unroll
            for (int cc = 0; cc < CPB; cc++) rs += __ldcg(&g_ex[b][cc][lane]);
            rs *= scale;
            a_s[lane] = entmax15_warp(rs, lane);
        }
        __syncthreads();
        if (wid == 0) {
            float rd = 0.0f;
#pragma unroll 8
            for (int n = 0; n < NSLOT; n++) rd = fmaf(a_s[n], tape_s[n * 33 + lane], rd);
            float hn = tanhf(hpre_s[lane] + rd);
            hnew_s[lane] = hn;
            g_ex[b][c][32 + lane] = hn;   // publish h_new slice
        }
        __syncthreads();
        {
            float wp0 = tape_s[o0 * 33 + lane] * hnew_s[lane];
            float wp1 = tape_s[o1 * 33 + lane] * hnew_s[lane];
#pragma unroll
            for (int o = 16; o > 0; o >>= 1) {
                wp0 += __shfl_xor_sync(F, wp0, o);
                wp1 += __shfl_xor_sync(F, wp1, o);
            }
            if (lane == 0) {
                g_ex[b][c][64 + o0] = wp0;
                g_ex[b][c][64 + o1] = wp1;
            }
        }
        __syncthreads();
        sync_id++;
        if (tid == 0) {
            __threadfence();
            atomicAdd(&g_cnt[b], 1);
            while (*cntp < CPB * sync_id) { }
            __threadfence();
        }
        __syncthreads();

        // ---- Phase C: gather h_new, w entmax, w_val matvec, tape update ----
        work_s[tid] = __ldcg(&g_ex[b][wid][32 + lane]);  // tid = wid*32+lane maps d exactly
        if (wid == 0) {
            float ws = 0.0f;
#pragma unroll
            for (int cc = 0; cc < CPB; cc++) ws += __ldcg(&g_ex[b][cc][64 + lane]);
            ws *= scale;
            bv_s[lane] = entmax15_warp(ws, lane);
        }
        __syncthreads();
        {
            float wa0 = 0.0f, wa1 = 0.0f;
            const float* ww0 = Ww_s + o0 * DDIM;
            const float* ww1 = Ww_s + o1 * DDIM;
#pragma unroll
            for (int kk = 0; kk < 16; kk++) {
                int d = lane + kk * 32;
                float hv = work_s[d];
                wa0 = fmaf(ww0[d], hv, wa0);
                wa1 = fmaf(ww1[d], hv, wa1);
            }
#pragma unroll
            for (int o = 16; o > 0; o >>= 1) {
                wa0 += __shfl_xor_sync(F, wa0, o);
                wa1 += __shfl_xor_sync(F, wa1, o);
            }
            if (lane == 0) { wval_s[o0] = wa0; wval_s[o1] = wa1; }
        }
        __syncthreads();
        for (int i = tid; i < NSLOT * SLICE; i += SCAN_THREADS) {
            int n = i >> 5, d2 = i & 31;
            float tv = tape_s[n * 33 + d2];
            tape_s[n * 33 + d2] = fmaf(bv_s[n], wval_s[d2] - tv, tv);
        }
        if (tid < SLICE)
            g_hs[((size_t)b * TSTEPS + t) * DDIM + dbase + tid] = hnew_s[tid];
        __syncthreads();
    }

    // ---- final outputs: tape_f and work_f ----
    const size_t TAPE_OFF = (size_t)BATCH * TSTEPS * DDIM;           // 4194304
    const size_t WORK_OFF = TAPE_OFF + (size_t)BATCH * NSLOT * DDIM; // 4325376
    for (int i = tid; i < NSLOT * SLICE; i += SCAN_THREADS) {
        int n = i >> 5, d2 = i & 31;
        dout[TAPE_OFF + ((size_t)b * NSLOT + n) * DDIM + dbase + d2] = tape_s[n * 33 + d2];
    }
    if (tid < SLICE)
        dout[WORK_OFF + (size_t)b * DDIM + dbase + tid] = work_s[dbase + tid];
}

// ---------------- launcher ----------------
extern "C" void kernel_launch(void* const* d_in, const int* in_sizes, int n_in,
                              void* d_out, int out_size)
{
    const float* x       = (const float*)d_in[0];
    const float* W_in    = (const float*)d_in[1];
    const float* W_out   = (const float*)d_in[2];
    const float* W_h     = (const float*)d_in[3];
    const float* W_x     = (const float*)d_in[4];
    const float* b_h     = (const float*)d_in[5];
    const float* W_write = (const float*)d_in[6];
    float* out = (float*)d_out;

    const int scan_smem = (2 * SLICE * DDIM + NSLOT * 33 + DDIM + 6 * 32) * (int)sizeof(float);
    cudaFuncSetAttribute(scan_kernel, cudaFuncAttributeMaxDynamicSharedMemorySize, scan_smem);

    dim3 blk(256);
    // xz = x @ W_in^T, fused silu -> g_xproj / g_siluz
    sgemm<0><<<dim3(1024 / 128, MROWS / 128), blk>>>(x, W_in, nullptr, MROWS, 1024, DDIM);
    // xw = x_proj @ W_x^T
    sgemm<1><<<dim3(DDIM / 128, MROWS / 128), blk>>>(nullptr, W_x, nullptr, MROWS, DDIM, DDIM);
    // reset barrier counters, then the recurrence
    init_kernel<<<1, 32>>>();
    scan_kernel<<<BATCH * CPB, SCAN_THREADS, scan_smem>>>(W_h, W_write, b_h, out);
    // out = (hs * silu(z)) @ W_out^T
    sgemm<2><<<dim3(DDIM / 128, MROWS / 128), blk>>>(nullptr, W_out, out, MROWS, DDIM, DDIM);
}